// round 3
// baseline (speedup 1.0000x reference)
#include <cuda_runtime.h>
#include <cstdint>

// Problem shape (fixed by the dataset):
//   features:        (BS=4, C=64, P=12000) float32
//   x_orig_indices:  (BS, P) int32  (JAX x64 disabled: "int64" is silently int32)
//   y_orig_indices:  (BS, P) int32
//   output pseudo:   (BS, C, NY=440, NX=500) float32
#define BS    4
#define CCH   64
#define NP    12000
#define NXP   500
#define NYP   440
#define CELLS (NXP * NYP)          // 220000
#define NOUT  (BS * CCH * CELLS)   // 56,320,000

// Allocation-free scratch (device globals, per the harness rules).
__device__ int g_winner[BS * CELLS];  // max point index p claiming each cell, or -1
__device__ int g_off[BS * NP];        // winning cell offset for point p, or -1

// ---------------------------------------------------------------------------
// Phase 0b: init winner array to -1 (output zeroing is done via cudaMemsetAsync)
// ---------------------------------------------------------------------------
__global__ void init_winner_kernel() {
    int i = blockIdx.x * blockDim.x + threadIdx.x;
    int4* w4 = reinterpret_cast<int4*>(g_winner);
    const int n4 = (BS * CELLS) / 4;  // 220000 — divisible by 4
    if (i < n4) {
        w4[i] = make_int4(-1, -1, -1, -1);
    }
}

// ---------------------------------------------------------------------------
// Phase 1: winner pass — last-update-in-P-order wins  ==  max p wins.
// One thread per (b, p). 48000 atomics into an L2-resident 3.5 MB array.
// ---------------------------------------------------------------------------
__global__ void winner_kernel(const int* __restrict__ xi,
                              const int* __restrict__ yi) {
    int i = blockIdx.x * blockDim.x + threadIdx.x;
    if (i >= BS * NP) return;
    int b = i / NP;
    int p = i - b * NP;

    int x = xi[i];
    int y = yi[i];
    // jnp.clip semantics
    x = x < 0 ? 0 : (x >= NXP ? NXP - 1 : x);
    y = y < 0 ? 0 : (y >= NYP ? NYP - 1 : y);
    int cell = y * NXP + x;

    atomicMax(&g_winner[b * CELLS + cell], p);
}

// ---------------------------------------------------------------------------
// Phase 2: per-point offset — coalesced hot array the scatter reads 64x each.
// ---------------------------------------------------------------------------
__global__ void off_kernel(const int* __restrict__ xi,
                           const int* __restrict__ yi) {
    int i = blockIdx.x * blockDim.x + threadIdx.x;
    if (i >= BS * NP) return;
    int b = i / NP;
    int p = i - b * NP;

    int x = xi[i];
    int y = yi[i];
    x = x < 0 ? 0 : (x >= NXP ? NXP - 1 : x);
    y = y < 0 ? 0 : (y >= NYP ? NYP - 1 : y);
    int cell = y * NXP + x;

    g_off[i] = (g_winner[b * CELLS + cell] == p) ? cell : -1;
}

// ---------------------------------------------------------------------------
// Phase 3: scatter — one thread per (b, c, p).
// features read fully coalesced (consecutive p); g_off read L2/L1-hot;
// one random 4B store per winning element. 3.07M threads for MLP.
// ---------------------------------------------------------------------------
__global__ void scatter_kernel(const float* __restrict__ feat,
                               float* __restrict__ out) {
    int i = blockIdx.x * blockDim.x + threadIdx.x;  // over BS*CCH*NP
    if (i >= BS * CCH * NP) return;
    int p  = i % NP;
    int bc = i / NP;          // b*CCH + c
    int b  = bc / CCH;

    int off = g_off[b * NP + p];
    if (off >= 0) {
        out[(long long)bc * CELLS + off] = feat[i];
    }
}

// ---------------------------------------------------------------------------
extern "C" void kernel_launch(void* const* d_in, const int* in_sizes, int n_in,
                              void* d_out, int out_size) {
    const float* feat = (const float*)d_in[0];
    const int*   xi   = (const int*)d_in[1];
    const int*   yi   = (const int*)d_in[2];
    float* out = (float*)d_out;

    // Zero the 225 MB output — driver memset runs at full HBM write BW.
    cudaMemsetAsync(out, 0, (size_t)out_size * sizeof(float), 0);

    {   // init winner to -1
        const int n4 = (BS * CELLS) / 4;
        int threads = 256;
        int blocks = (n4 + threads - 1) / threads;
        init_winner_kernel<<<blocks, threads>>>();
    }
    {   // winner pass
        int n = BS * NP;
        int threads = 256;
        int blocks = (n + threads - 1) / threads;
        winner_kernel<<<blocks, threads>>>(xi, yi);
    }
    {   // offset pass
        int n = BS * NP;
        int threads = 256;
        int blocks = (n + threads - 1) / threads;
        off_kernel<<<blocks, threads>>>(xi, yi);
    }
    {   // scatter
        int n = BS * CCH * NP;
        int threads = 256;
        int blocks = (n + threads - 1) / threads;
        scatter_kernel<<<blocks, threads>>>(feat, out);
    }
}

// round 4
// speedup vs baseline: 1.7989x; 1.7989x over previous
#include <cuda_runtime.h>
#include <cstdint>

// Problem shape (fixed by the dataset):
//   features:        (BS=4, C=64, P=12000) float32
//   x_orig_indices:  (BS, P) int32  (JAX x64 disabled: "int64" is silently int32)
//   y_orig_indices:  (BS, P) int32
//   output pseudo:   (BS, C, NY=440, NX=500) float32
#define BS    4
#define CCH   64
#define NP    12000
#define NXP   500
#define NYP   440
#define CELLS (NXP * NYP)          // 220000  (divisible by 4)
#define NOUT  (BS * CCH * CELLS)   // 56,320,000

// Allocation-free scratch (device global, per harness rules).
__device__ int g_winner[BS * CELLS];  // max point index p claiming each cell, or -1

// ---------------------------------------------------------------------------
// Phase 0: init winner array to -1 (vectorized).
// ---------------------------------------------------------------------------
__global__ void init_winner_kernel() {
    int i = blockIdx.x * blockDim.x + threadIdx.x;
    int4* w4 = reinterpret_cast<int4*>(g_winner);
    const int n4 = (BS * CELLS) / 4;  // 220000
    if (i < n4) {
        w4[i] = make_int4(-1, -1, -1, -1);
    }
}

// ---------------------------------------------------------------------------
// Phase 1: winner pass — JAX sequential .set semantics == last p wins == max p.
// 48000 atomicMax into an L2-resident 3.5 MB array. ~few us.
// ---------------------------------------------------------------------------
__global__ void winner_kernel(const int* __restrict__ xi,
                              const int* __restrict__ yi) {
    int i = blockIdx.x * blockDim.x + threadIdx.x;
    if (i >= BS * NP) return;
    int b = i / NP;
    int p = i - b * NP;

    int x = xi[i];
    int y = yi[i];
    // jnp.clip semantics
    x = x < 0 ? 0 : (x >= NXP ? NXP - 1 : x);
    y = y < 0 ? 0 : (y >= NYP ? NYP - 1 : y);
    int cell = y * NXP + x;

    atomicMax(&g_winner[b * CELLS + cell], p);
}

// ---------------------------------------------------------------------------
// Phase 2: fused zero-fill + gather. One thread per 4 output cells.
//   out[b][c][cell] = winner[b][cell] >= 0 ? feat[b][c][winner] : 0
// Stores: fully coalesced float4 (the whole 225 MB output, replaces memset).
// Winner reads: int4, coalesced, 64x-reused -> L2-hot.
// Feat reads: ~5.3% of cells, confined to one 48KB row per (b,c) -> L1/L2-hot.
// ---------------------------------------------------------------------------
__global__ void gather_kernel(const float* __restrict__ feat,
                              float* __restrict__ out) {
    const int n4 = NOUT / 4;                       // 14,080,000
    int i = blockIdx.x * blockDim.x + threadIdx.x; // one thread = 4 cells
    if (i >= n4) return;

    const int cells4 = CELLS / 4;                  // 55000
    int bc    = i / cells4;                        // b*CCH + c  (same for all 4 cells)
    int cell4 = i - bc * cells4;
    int b     = bc >> 6;                           // / CCH

    // Coalesced winner read (consecutive cells within one batch).
    int4 w = reinterpret_cast<const int4*>(g_winner + b * CELLS)[cell4];

    const float* frow = feat + bc * NP;            // 48KB row, L1-resident
    float4 v;
    v.x = (w.x >= 0) ? __ldg(frow + w.x) : 0.0f;
    v.y = (w.y >= 0) ? __ldg(frow + w.y) : 0.0f;
    v.z = (w.z >= 0) ? __ldg(frow + w.z) : 0.0f;
    v.w = (w.w >= 0) ? __ldg(frow + w.w) : 0.0f;

    // Fully coalesced 16B store.
    reinterpret_cast<float4*>(out)[i] = v;
}

// ---------------------------------------------------------------------------
extern "C" void kernel_launch(void* const* d_in, const int* in_sizes, int n_in,
                              void* d_out, int out_size) {
    const float* feat = (const float*)d_in[0];
    const int*   xi   = (const int*)d_in[1];
    const int*   yi   = (const int*)d_in[2];
    float* out = (float*)d_out;

    {   // init winner to -1
        const int n4 = (BS * CELLS) / 4;
        int threads = 256;
        int blocks = (n4 + threads - 1) / threads;
        init_winner_kernel<<<blocks, threads>>>();
    }
    {   // winner pass
        int n = BS * NP;
        int threads = 256;
        int blocks = (n + threads - 1) / threads;
        winner_kernel<<<blocks, threads>>>(xi, yi);
    }
    {   // fused zero + gather (writes every output element)
        const int n4 = NOUT / 4;
        int threads = 256;
        int blocks = (n4 + threads - 1) / threads;  // 55000 blocks
        gather_kernel<<<blocks, threads>>>(feat, out);
    }
}